// round 1
// baseline (speedup 1.0000x reference)
#include <cuda_runtime.h>
#include <math.h>

// Problem constants
#define BATCH 256
#define EDIM 128
#define HDIM 128
#define NTOK 511     // tokens per batch (2^9 - 1)
#define NARITY 255   // internal nodes per batch (2^8 - 1)

// Tiling
#define TM 32        // rows (nodes) per block
#define TJ 32        // output columns per block
#define TK 16        // K-chunk staged in shared

// Ping-pong scratch for h and c: max 256 nodes/batch at leaf level.
// 2 * 2 * 256*256*128 floats = 134 MB static device memory (allowed).
__device__ float g_h[2][BATCH * 256 * HDIM];
__device__ float g_c[2][BATCH * 256 * HDIM];

__device__ __forceinline__ float sigmoid_(float x) {
    return 1.0f / (1.0f + expf(-x));
}
__device__ __forceinline__ float tanh_(float x) {
    // 1 - 2/(e^{2x}+1): accurate and safe under fast-math (uses expf only)
    return 1.0f - 2.0f / (expf(2.0f * x) + 1.0f);
}

// ---------------------------------------------------------------------------
// Leaf kernel: h = tanh(emb[tok] @ W[3] + bW[3]), c = 0
// rows = BATCH*256, grid.x = rows/TM, grid.y = HDIM/TJ
// ---------------------------------------------------------------------------
__global__ __launch_bounds__(256, 2)
void leaf_kernel(const int* __restrict__ tokens,
                 const float* __restrict__ emb,
                 const float* __restrict__ W,
                 const float* __restrict__ bW)
{
    __shared__ __align__(16) float sh_x[TM][EDIM];
    __shared__ __align__(16) float sh_w[TK][TJ];

    float* __restrict__ h_out = g_h[0];
    float* __restrict__ c_out = g_c[0];

    const int tid  = threadIdx.x;
    const int lane = tid & 31;
    const int rg   = tid >> 5;          // 0..7 (warp id = row group)
    const int colb = blockIdx.y * TJ;
    const int col  = colb + lane;
    const int row0 = blockIdx.x * TM;

    // Stage x rows (warp rg loads its 4 rows, float4-coalesced)
#pragma unroll
    for (int i = 0; i < 4; i++) {
        const int r   = rg * 4 + i;
        const int row = row0 + r;
        const int b   = row >> 8;
        const int j   = row & 255;
        const int tok = __ldg(&tokens[b * NTOK + 255 + j]);
        *(float4*)&sh_x[r][lane * 4] =
            *(const float4*)(emb + (size_t)tok * EDIM + lane * 4);
    }

    float acc[4] = {0.f, 0.f, 0.f, 0.f};
    const float* __restrict__ W3 = W + 3 * EDIM * HDIM;

    for (int kc = 0; kc < EDIM / TK; kc++) {
        __syncthreads();
#pragma unroll
        for (int j = 0; j < 2; j++) {      // 16*32 = 512 elems, 2/thread
            const int idx = j * 256 + tid;
            const int kk  = idx >> 5;
            const int c   = idx & 31;
            sh_w[kk][c] = __ldg(&W3[(kc * TK + kk) * HDIM + colb + c]);
        }
        __syncthreads();
#pragma unroll
        for (int kk = 0; kk < TK; kk += 4) {
            const int k = kc * TK + kk;
#pragma unroll
            for (int i = 0; i < 4; i++) {
                const float4 xv = *(const float4*)&sh_x[rg * 4 + i][k];
                acc[i] += xv.x * sh_w[kk + 0][lane];
                acc[i] += xv.y * sh_w[kk + 1][lane];
                acc[i] += xv.z * sh_w[kk + 2][lane];
                acc[i] += xv.w * sh_w[kk + 3][lane];
            }
        }
    }

    const float bias = __ldg(&bW[3 * HDIM + col]);
#pragma unroll
    for (int i = 0; i < 4; i++) {
        const int row = row0 + rg * 4 + i;
        h_out[(size_t)row * HDIM + col] = tanh_(acc[i] + bias);
        c_out[(size_t)row * HDIM + col] = 0.0f;
    }
}

// ---------------------------------------------------------------------------
// Internal-level kernel: fused Wx/Ubin/Uun GEMMs + LSTM pointwise.
// Level l: cnt = 2^l nodes/batch. rows = BATCH*cnt (row = b*cnt + n).
// Children live at rows b*2*cnt + 2n (+1) of the input buffers.
// ---------------------------------------------------------------------------
__global__ __launch_bounds__(256, 2)
void level_kernel(const int* __restrict__ tokens,
                  const int* __restrict__ arity,
                  const float* __restrict__ emb,
                  const float* __restrict__ W,    const float* __restrict__ bW,
                  const float* __restrict__ Ubin, const float* __restrict__ bUbin,
                  const float* __restrict__ Uun,  const float* __restrict__ bUun,
                  int pin, int pout, int lcnt)
{
    __shared__ __align__(16) float sh_hl[TM][HDIM];
    __shared__ __align__(16) float sh_b [TM][HDIM];   // x (phase A), then h_r (phase B)
    __shared__ __align__(16) float sh_w [5][TK][TJ];

    const float* __restrict__ h_in  = g_h[pin];
    const float* __restrict__ c_in  = g_c[pin];
    float* __restrict__ h_out = g_h[pout];
    float* __restrict__ c_out = g_c[pout];

    const int tid  = threadIdx.x;
    const int lane = tid & 31;
    const int rg   = tid >> 5;
    const int cnt  = 1 << lcnt;
    const int o2   = cnt - 1;
    const int colb = blockIdx.y * TJ;
    const int col  = colb + lane;
    const int row0 = blockIdx.x * TM;

    // Stage x (into sh_b) and h_l
#pragma unroll
    for (int i = 0; i < 4; i++) {
        const int r   = rg * 4 + i;
        const int row = row0 + r;
        const int b   = row >> lcnt;
        const int n   = row & (cnt - 1);
        const int tok = __ldg(&tokens[b * NTOK + o2 + n]);
        *(float4*)&sh_b[r][lane * 4] =
            *(const float4*)(emb + (size_t)tok * EDIM + lane * 4);
        const int childrow = (b << (lcnt + 1)) + 2 * n;
        *(float4*)&sh_hl[r][lane * 4] =
            *(const float4*)(h_in + (size_t)childrow * HDIM + lane * 4);
    }

    float awx[4][4];
    float aub[5][4];
    float auu[4][4];
#pragma unroll
    for (int g = 0; g < 4; g++)
#pragma unroll
        for (int i = 0; i < 4; i++) { awx[g][i] = 0.f; auu[g][i] = 0.f; }
#pragma unroll
    for (int g = 0; g < 5; g++)
#pragma unroll
        for (int i = 0; i < 4; i++) aub[g][i] = 0.f;

    // ---- Phase A: Wx = x @ W[g] (g=0..3, K=128, x in sh_b) ----
    for (int kc = 0; kc < EDIM / TK; kc++) {
        __syncthreads();
#pragma unroll
        for (int j = 0; j < 8; j++) {      // 4*16*32 = 2048 elems
            const int idx = j * 256 + tid;
            const int g   = idx >> 9;
            const int kk  = (idx >> 5) & 15;
            const int c   = idx & 31;
            sh_w[g][kk][c] = __ldg(&W[((g << 7) + kc * TK + kk) * HDIM + colb + c]);
        }
        __syncthreads();
#pragma unroll
        for (int kk = 0; kk < TK; kk += 4) {
            const int k = kc * TK + kk;
#pragma unroll
            for (int i = 0; i < 4; i++) {
                const float4 xv = *(const float4*)&sh_b[rg * 4 + i][k];
                const float xs[4] = {xv.x, xv.y, xv.z, xv.w};
#pragma unroll
                for (int q = 0; q < 4; q++)
#pragma unroll
                    for (int g = 0; g < 4; g++)
                        awx[g][i] += xs[q] * sh_w[g][kk + q][lane];
            }
        }
    }

    // Restage: h_r into sh_b
    __syncthreads();
#pragma unroll
    for (int i = 0; i < 4; i++) {
        const int r   = rg * 4 + i;
        const int row = row0 + r;
        const int b   = row >> lcnt;
        const int n   = row & (cnt - 1);
        const int childrow = (b << (lcnt + 1)) + 2 * n + 1;
        *(float4*)&sh_b[r][lane * 4] =
            *(const float4*)(h_in + (size_t)childrow * HDIM + lane * 4);
    }

    // ---- Phase B: Ub = [h_l, h_r] @ Ubin[g] (g=0..4, K=256) ----
    for (int half = 0; half < 2; half++) {
        const float (*src)[HDIM] = half ? (const float(*)[HDIM])sh_b
                                        : (const float(*)[HDIM])sh_hl;
        for (int kc = 0; kc < EDIM / TK; kc++) {
            __syncthreads();
#pragma unroll
            for (int j = 0; j < 10; j++) {  // 5*16*32 = 2560 elems
                const int idx = j * 256 + tid;
                const int g   = idx / 512;
                const int kk  = (idx >> 5) & 15;
                const int c   = idx & 31;
                sh_w[g][kk][c] =
                    __ldg(&Ubin[(g * 256 + half * 128 + kc * TK + kk) * HDIM + colb + c]);
            }
            __syncthreads();
#pragma unroll
            for (int kk = 0; kk < TK; kk += 4) {
                const int k = kc * TK + kk;
#pragma unroll
                for (int i = 0; i < 4; i++) {
                    const float4 xv = *(const float4*)&src[rg * 4 + i][k];
                    const float xs[4] = {xv.x, xv.y, xv.z, xv.w};
#pragma unroll
                    for (int q = 0; q < 4; q++)
#pragma unroll
                        for (int g = 0; g < 5; g++)
                            aub[g][i] += xs[q] * sh_w[g][kk + q][lane];
                }
            }
        }
    }

    // ---- Phase C: Uu = h_l @ Uun[g] (g=0..3, K=128) ----
    for (int kc = 0; kc < EDIM / TK; kc++) {
        __syncthreads();
#pragma unroll
        for (int j = 0; j < 8; j++) {
            const int idx = j * 256 + tid;
            const int g   = idx >> 9;
            const int kk  = (idx >> 5) & 15;
            const int c   = idx & 31;
            sh_w[g][kk][c] = __ldg(&Uun[((g << 7) + kc * TK + kk) * HDIM + colb + c]);
        }
        __syncthreads();
#pragma unroll
        for (int kk = 0; kk < TK; kk += 4) {
            const int k = kc * TK + kk;
#pragma unroll
            for (int i = 0; i < 4; i++) {
                const float4 xv = *(const float4*)&sh_hl[rg * 4 + i][k];
                const float xs[4] = {xv.x, xv.y, xv.z, xv.w};
#pragma unroll
                for (int q = 0; q < 4; q++)
#pragma unroll
                    for (int g = 0; g < 4; g++)
                        auu[g][i] += xs[q] * sh_w[g][kk + q][lane];
            }
        }
    }

    // ---- Epilogue: biases + gate nonlinearities + cell update ----
    float bwx[4], bub[5], buu[4];
#pragma unroll
    for (int g = 0; g < 4; g++) {
        bwx[g] = __ldg(&bW[g * HDIM + col]);
        buu[g] = __ldg(&bUun[g * HDIM + col]);
    }
#pragma unroll
    for (int g = 0; g < 5; g++) bub[g] = __ldg(&bUbin[g * HDIM + col]);

#pragma unroll
    for (int i = 0; i < 4; i++) {
        const int row = row0 + rg * 4 + i;
        const int b   = row >> lcnt;
        const int n   = row & (cnt - 1);
        const int ar  = __ldg(&arity[b * NARITY + o2 + n]);
        const int childrow = (b << (lcnt + 1)) + 2 * n;
        const float cl = __ldg(&c_in[(size_t)childrow * HDIM + col]);

        const float wx0 = awx[0][i] + bwx[0];
        const float wx1 = awx[1][i] + bwx[1];
        const float wx2 = awx[2][i] + bwx[2];
        const float wx3 = awx[3][i] + bwx[3];

        float hv, cv;
        if (ar == 1) {  // binary node
            const float cr = __ldg(&c_in[(size_t)(childrow + 1) * HDIM + col]);
            const float ig = sigmoid_(wx0 + aub[0][i] + bub[0]);
            const float fl = sigmoid_(wx1 + aub[1][i] + bub[1]);
            const float fr = sigmoid_(wx1 + aub[2][i] + bub[2]);
            const float og = sigmoid_(wx2 + aub[3][i] + bub[3]);
            const float ug = tanh_   (wx3 + aub[4][i] + bub[4]);
            cv = ig * ug + fl * cl + fr * cr;
            hv = og * tanh_(cv);
        } else {        // unary node (left child only)
            const float ig = sigmoid_(wx0 + auu[0][i] + buu[0]);
            const float fg = sigmoid_(wx1 + auu[1][i] + buu[1]);
            const float og = sigmoid_(wx2 + auu[2][i] + buu[2]);
            const float ug = tanh_   (wx3 + auu[3][i] + buu[3]);
            cv = ig * ug + fg * cl;
            hv = og * tanh_(cv);
        }
        h_out[(size_t)row * HDIM + col] = hv;
        c_out[(size_t)row * HDIM + col] = cv;
    }
}

// ---------------------------------------------------------------------------
// Final copy: out[0:32768] = h_root (B,H), out[32768:65536] = c_root (B,H)
// ---------------------------------------------------------------------------
__global__ void copy_out_kernel(int pin, float* __restrict__ out)
{
    const int t = blockIdx.x * blockDim.x + threadIdx.x;  // 0..32767
    out[t]                      = g_h[pin][t];
    out[BATCH * HDIM + t]       = g_c[pin][t];
}

// ---------------------------------------------------------------------------
extern "C" void kernel_launch(void* const* d_in, const int* in_sizes, int n_in,
                              void* d_out, int out_size)
{
    const int*   tokens = (const int*)  d_in[0];
    const int*   arity  = (const int*)  d_in[1];
    const float* emb    = (const float*)d_in[2];
    const float* W      = (const float*)d_in[3];
    const float* bW     = (const float*)d_in[4];
    const float* Ubin   = (const float*)d_in[5];
    const float* bUbin  = (const float*)d_in[6];
    const float* Uun    = (const float*)d_in[7];
    const float* bUun   = (const float*)d_in[8];
    float* out = (float*)d_out;

    // Leaves: 65536 rows -> grid (2048, 4), writes buffers [0]
    {
        dim3 grid(BATCH * 256 / TM, HDIM / TJ);
        leaf_kernel<<<grid, 256>>>(tokens, emb, W, bW);
    }

    // Levels 7..0
    int pin = 0;
    for (int l = 7; l >= 0; l--) {
        const int pout = 1 - pin;
        dim3 grid((BATCH << l) / TM, HDIM / TJ);
        level_kernel<<<grid, 256>>>(tokens, arity, emb,
                                    W, bW, Ubin, bUbin, Uun, bUun,
                                    pin, pout, l);
        pin = pout;
    }

    // Root outputs
    copy_out_kernel<<<(BATCH * HDIM) / 256, 256>>>(pin, out);
}

// round 2
// speedup vs baseline: 1.0009x; 1.0009x over previous
#include <cuda_runtime.h>
#include <math.h>

// Problem constants
#define BATCH 256
#define EDIM 128
#define HDIM 128
#define NTOK 511     // tokens per batch (2^9 - 1)
#define NARITY 255   // internal nodes per batch (2^8 - 1)

// Tiling
#define TM 32        // rows (nodes) per block
#define TJ 32        // output columns per block
#define TK 16        // K-chunk staged in shared

// Ping-pong scratch for h and c: max 256 nodes/batch at leaf level.
// 2 * 2 * 256*256*128 floats = 134 MB static device memory (allowed).
__device__ float g_h[2][BATCH * 256 * HDIM];
__device__ float g_c[2][BATCH * 256 * HDIM];

__device__ __forceinline__ float sigmoid_(float x) {
    return 1.0f / (1.0f + expf(-x));
}
__device__ __forceinline__ float tanh_(float x) {
    // 1 - 2/(e^{2x}+1): accurate and safe under fast-math (uses expf only)
    return 1.0f - 2.0f / (expf(2.0f * x) + 1.0f);
}

// ---------------------------------------------------------------------------
// Leaf kernel: h = tanh(emb[tok] @ W[3] + bW[3]), c = 0
// rows = BATCH*256, grid.x = rows/TM, grid.y = HDIM/TJ
// ---------------------------------------------------------------------------
__global__ __launch_bounds__(256, 2)
void leaf_kernel(const int* __restrict__ tokens,
                 const float* __restrict__ emb,
                 const float* __restrict__ W,
                 const float* __restrict__ bW)
{
    __shared__ __align__(16) float sh_x[TM][EDIM];
    __shared__ __align__(16) float sh_w[TK][TJ];

    float* __restrict__ h_out = g_h[0];
    float* __restrict__ c_out = g_c[0];

    const int tid  = threadIdx.x;
    const int lane = tid & 31;
    const int rg   = tid >> 5;          // 0..7 (warp id = row group)
    const int colb = blockIdx.y * TJ;
    const int col  = colb + lane;
    const int row0 = blockIdx.x * TM;

    // Stage x rows (warp rg loads its 4 rows, float4-coalesced)
#pragma unroll
    for (int i = 0; i < 4; i++) {
        const int r   = rg * 4 + i;
        const int row = row0 + r;
        const int b   = row >> 8;
        const int j   = row & 255;
        const int tok = __ldg(&tokens[b * NTOK + 255 + j]);
        *(float4*)&sh_x[r][lane * 4] =
            *(const float4*)(emb + (size_t)tok * EDIM + lane * 4);
    }

    float acc[4] = {0.f, 0.f, 0.f, 0.f};
    const float* __restrict__ W3 = W + 3 * EDIM * HDIM;

    for (int kc = 0; kc < EDIM / TK; kc++) {
        __syncthreads();
#pragma unroll
        for (int j = 0; j < 2; j++) {      // 16*32 = 512 elems, 2/thread
            const int idx = j * 256 + tid;
            const int kk  = idx >> 5;
            const int c   = idx & 31;
            sh_w[kk][c] = __ldg(&W3[(kc * TK + kk) * HDIM + colb + c]);
        }
        __syncthreads();
#pragma unroll
        for (int kk = 0; kk < TK; kk += 4) {
            const int k = kc * TK + kk;
#pragma unroll
            for (int i = 0; i < 4; i++) {
                const float4 xv = *(const float4*)&sh_x[rg * 4 + i][k];
                acc[i] += xv.x * sh_w[kk + 0][lane];
                acc[i] += xv.y * sh_w[kk + 1][lane];
                acc[i] += xv.z * sh_w[kk + 2][lane];
                acc[i] += xv.w * sh_w[kk + 3][lane];
            }
        }
    }

    const float bias = __ldg(&bW[3 * HDIM + col]);
#pragma unroll
    for (int i = 0; i < 4; i++) {
        const int row = row0 + rg * 4 + i;
        h_out[(size_t)row * HDIM + col] = tanh_(acc[i] + bias);
        c_out[(size_t)row * HDIM + col] = 0.0f;
    }
}

// ---------------------------------------------------------------------------
// Internal-level kernel: fused Wx/Ubin/Uun GEMMs + LSTM pointwise.
// Level l: cnt = 2^l nodes/batch. rows = BATCH*cnt (row = b*cnt + n).
// Children live at rows b*2*cnt + 2n (+1) of the input buffers.
// ---------------------------------------------------------------------------
__global__ __launch_bounds__(256, 2)
void level_kernel(const int* __restrict__ tokens,
                  const int* __restrict__ arity,
                  const float* __restrict__ emb,
                  const float* __restrict__ W,    const float* __restrict__ bW,
                  const float* __restrict__ Ubin, const float* __restrict__ bUbin,
                  const float* __restrict__ Uun,  const float* __restrict__ bUun,
                  int pin, int pout, int lcnt)
{
    __shared__ __align__(16) float sh_hl[TM][HDIM];
    __shared__ __align__(16) float sh_b [TM][HDIM];   // x (phase A), then h_r (phase B)
    __shared__ __align__(16) float sh_w [5][TK][TJ];

    const float* __restrict__ h_in  = g_h[pin];
    const float* __restrict__ c_in  = g_c[pin];
    float* __restrict__ h_out = g_h[pout];
    float* __restrict__ c_out = g_c[pout];

    const int tid  = threadIdx.x;
    const int lane = tid & 31;
    const int rg   = tid >> 5;
    const int cnt  = 1 << lcnt;
    const int o2   = cnt - 1;
    const int colb = blockIdx.y * TJ;
    const int col  = colb + lane;
    const int row0 = blockIdx.x * TM;

    // Stage x (into sh_b) and h_l
#pragma unroll
    for (int i = 0; i < 4; i++) {
        const int r   = rg * 4 + i;
        const int row = row0 + r;
        const int b   = row >> lcnt;
        const int n   = row & (cnt - 1);
        const int tok = __ldg(&tokens[b * NTOK + o2 + n]);
        *(float4*)&sh_b[r][lane * 4] =
            *(const float4*)(emb + (size_t)tok * EDIM + lane * 4);
        const int childrow = (b << (lcnt + 1)) + 2 * n;
        *(float4*)&sh_hl[r][lane * 4] =
            *(const float4*)(h_in + (size_t)childrow * HDIM + lane * 4);
    }

    float awx[4][4];
    float aub[5][4];
    float auu[4][4];
#pragma unroll
    for (int g = 0; g < 4; g++)
#pragma unroll
        for (int i = 0; i < 4; i++) { awx[g][i] = 0.f; auu[g][i] = 0.f; }
#pragma unroll
    for (int g = 0; g < 5; g++)
#pragma unroll
        for (int i = 0; i < 4; i++) aub[g][i] = 0.f;

    // ---- Phase A: Wx = x @ W[g] (g=0..3, K=128, x in sh_b) ----
    for (int kc = 0; kc < EDIM / TK; kc++) {
        __syncthreads();
#pragma unroll
        for (int j = 0; j < 8; j++) {      // 4*16*32 = 2048 elems
            const int idx = j * 256 + tid;
            const int g   = idx >> 9;
            const int kk  = (idx >> 5) & 15;
            const int c   = idx & 31;
            sh_w[g][kk][c] = __ldg(&W[((g << 7) + kc * TK + kk) * HDIM + colb + c]);
        }
        __syncthreads();
#pragma unroll
        for (int kk = 0; kk < TK; kk += 4) {
            const int k = kc * TK + kk;
#pragma unroll
            for (int i = 0; i < 4; i++) {
                const float4 xv = *(const float4*)&sh_b[rg * 4 + i][k];
                const float xs[4] = {xv.x, xv.y, xv.z, xv.w};
#pragma unroll
                for (int q = 0; q < 4; q++)
#pragma unroll
                    for (int g = 0; g < 4; g++)
                        awx[g][i] += xs[q] * sh_w[g][kk + q][lane];
            }
        }
    }

    // Restage: h_r into sh_b
    __syncthreads();
#pragma unroll
    for (int i = 0; i < 4; i++) {
        const int r   = rg * 4 + i;
        const int row = row0 + r;
        const int b   = row >> lcnt;
        const int n   = row & (cnt - 1);
        const int childrow = (b << (lcnt + 1)) + 2 * n + 1;
        *(float4*)&sh_b[r][lane * 4] =
            *(const float4*)(h_in + (size_t)childrow * HDIM + lane * 4);
    }

    // ---- Phase B: Ub = [h_l, h_r] @ Ubin[g] (g=0..4, K=256) ----
    for (int half = 0; half < 2; half++) {
        const float (*src)[HDIM] = half ? (const float(*)[HDIM])sh_b
                                        : (const float(*)[HDIM])sh_hl;
        for (int kc = 0; kc < EDIM / TK; kc++) {
            __syncthreads();
#pragma unroll
            for (int j = 0; j < 10; j++) {  // 5*16*32 = 2560 elems
                const int idx = j * 256 + tid;
                const int g   = idx / 512;
                const int kk  = (idx >> 5) & 15;
                const int c   = idx & 31;
                sh_w[g][kk][c] =
                    __ldg(&Ubin[(g * 256 + half * 128 + kc * TK + kk) * HDIM + colb + c]);
            }
            __syncthreads();
#pragma unroll
            for (int kk = 0; kk < TK; kk += 4) {
                const int k = kc * TK + kk;
#pragma unroll
                for (int i = 0; i < 4; i++) {
                    const float4 xv = *(const float4*)&src[rg * 4 + i][k];
                    const float xs[4] = {xv.x, xv.y, xv.z, xv.w};
#pragma unroll
                    for (int q = 0; q < 4; q++)
#pragma unroll
                        for (int g = 0; g < 5; g++)
                            aub[g][i] += xs[q] * sh_w[g][kk + q][lane];
                }
            }
        }
    }

    // ---- Phase C: Uu = h_l @ Uun[g] (g=0..3, K=128) ----
    for (int kc = 0; kc < EDIM / TK; kc++) {
        __syncthreads();
#pragma unroll
        for (int j = 0; j < 8; j++) {
            const int idx = j * 256 + tid;
            const int g   = idx >> 9;
            const int kk  = (idx >> 5) & 15;
            const int c   = idx & 31;
            sh_w[g][kk][c] = __ldg(&Uun[((g << 7) + kc * TK + kk) * HDIM + colb + c]);
        }
        __syncthreads();
#pragma unroll
        for (int kk = 0; kk < TK; kk += 4) {
            const int k = kc * TK + kk;
#pragma unroll
            for (int i = 0; i < 4; i++) {
                const float4 xv = *(const float4*)&sh_hl[rg * 4 + i][k];
                const float xs[4] = {xv.x, xv.y, xv.z, xv.w};
#pragma unroll
                for (int q = 0; q < 4; q++)
#pragma unroll
                    for (int g = 0; g < 4; g++)
                        auu[g][i] += xs[q] * sh_w[g][kk + q][lane];
            }
        }
    }

    // ---- Epilogue: biases + gate nonlinearities + cell update ----
    float bwx[4], bub[5], buu[4];
#pragma unroll
    for (int g = 0; g < 4; g++) {
        bwx[g] = __ldg(&bW[g * HDIM + col]);
        buu[g] = __ldg(&bUun[g * HDIM + col]);
    }
#pragma unroll
    for (int g = 0; g < 5; g++) bub[g] = __ldg(&bUbin[g * HDIM + col]);

#pragma unroll
    for (int i = 0; i < 4; i++) {
        const int row = row0 + rg * 4 + i;
        const int b   = row >> lcnt;
        const int n   = row & (cnt - 1);
        const int ar  = __ldg(&arity[b * NARITY + o2 + n]);
        const int childrow = (b << (lcnt + 1)) + 2 * n;
        const float cl = __ldg(&c_in[(size_t)childrow * HDIM + col]);

        const float wx0 = awx[0][i] + bwx[0];
        const float wx1 = awx[1][i] + bwx[1];
        const float wx2 = awx[2][i] + bwx[2];
        const float wx3 = awx[3][i] + bwx[3];

        float hv, cv;
        if (ar == 1) {  // binary node
            const float cr = __ldg(&c_in[(size_t)(childrow + 1) * HDIM + col]);
            const float ig = sigmoid_(wx0 + aub[0][i] + bub[0]);
            const float fl = sigmoid_(wx1 + aub[1][i] + bub[1]);
            const float fr = sigmoid_(wx1 + aub[2][i] + bub[2]);
            const float og = sigmoid_(wx2 + aub[3][i] + bub[3]);
            const float ug = tanh_   (wx3 + aub[4][i] + bub[4]);
            cv = ig * ug + fl * cl + fr * cr;
            hv = og * tanh_(cv);
        } else {        // unary node (left child only)
            const float ig = sigmoid_(wx0 + auu[0][i] + buu[0]);
            const float fg = sigmoid_(wx1 + auu[1][i] + buu[1]);
            const float og = sigmoid_(wx2 + auu[2][i] + buu[2]);
            const float ug = tanh_   (wx3 + auu[3][i] + buu[3]);
            cv = ig * ug + fg * cl;
            hv = og * tanh_(cv);
        }
        h_out[(size_t)row * HDIM + col] = hv;
        c_out[(size_t)row * HDIM + col] = cv;
    }
}

// ---------------------------------------------------------------------------
// Final copy: out[0:32768] = h_root (B,H), out[32768:65536] = c_root (B,H)
// ---------------------------------------------------------------------------
__global__ void copy_out_kernel(int pin, float* __restrict__ out)
{
    const int t = blockIdx.x * blockDim.x + threadIdx.x;  // 0..32767
    out[t]                      = g_h[pin][t];
    out[BATCH * HDIM + t]       = g_c[pin][t];
}

// ---------------------------------------------------------------------------
extern "C" void kernel_launch(void* const* d_in, const int* in_sizes, int n_in,
                              void* d_out, int out_size)
{
    const int*   tokens = (const int*)  d_in[0];
    const int*   arity  = (const int*)  d_in[1];
    const float* emb    = (const float*)d_in[2];
    const float* W      = (const float*)d_in[3];
    const float* bW     = (const float*)d_in[4];
    const float* Ubin   = (const float*)d_in[5];
    const float* bUbin  = (const float*)d_in[6];
    const float* Uun    = (const float*)d_in[7];
    const float* bUun   = (const float*)d_in[8];
    float* out = (float*)d_out;

    // Leaves: 65536 rows -> grid (2048, 4), writes buffers [0]
    {
        dim3 grid(BATCH * 256 / TM, HDIM / TJ);
        leaf_kernel<<<grid, 256>>>(tokens, emb, W, bW);
    }

    // Levels 7..0
    int pin = 0;
    for (int l = 7; l >= 0; l--) {
        const int pout = 1 - pin;
        dim3 grid((BATCH << l) / TM, HDIM / TJ);
        level_kernel<<<grid, 256>>>(tokens, arity, emb,
                                    W, bW, Ubin, bUbin, Uun, bUun,
                                    pin, pout, l);
        pin = pout;
    }

    // Root outputs
    copy_out_kernel<<<(BATCH * HDIM) / 256, 256>>>(pin, out);
}